// round 11
// baseline (speedup 1.0000x reference)
#include <cuda_runtime.h>
#include <math.h>

#define TILE_E 128
#define HID 64
#define INF_DIM 32
#define THREADS 256
#define MAXN 51200
#define MAXE 1605640
#define STR 130        // sHT row stride in floats (8B-aligned LDS.64, conflict-light)

typedef unsigned long long ull;

// ---- packed f32x2 helpers (PTX-only; ptxas never auto-fuses) ----
__device__ __forceinline__ void ffma2(ull &acc, ull a, ull b) {
    asm("fma.rn.f32x2 %0, %1, %2, %0;" : "+l"(acc) : "l"(a), "l"(b));
}
__device__ __forceinline__ ull add2(ull a, ull b) {
    ull r; asm("add.rn.f32x2 %0, %1, %2;" : "=l"(r) : "l"(a), "l"(b)); return r;
}
__device__ __forceinline__ ull dup2(float v) {
    ull r; asm("mov.b64 %0, {%1, %1};" : "=l"(r) : "f"(v)); return r;
}
__device__ __forceinline__ float2 unpk(ull p) {
    float2 f; asm("mov.b64 {%0, %1}, %2;" : "=f"(f.x), "=f"(f.y) : "l"(p)); return f;
}

// Scratch (no cudaMalloc allowed)
__device__ unsigned int g_agg[(size_t)MAXN * HID];
__device__ float g_Qd[(size_t)MAXN * HID];   // x@(W1a-W1b) + b1
__device__ float g_Qs[(size_t)MAXN * HID];   // x@W1b
__device__ int g_cnt[MAXN];    // per-dst histogram
__device__ int g_cur[MAXN];    // scatter cursors (exclusive prefix of cnt)
__device__ int g_perm[MAXE];   // edge ids sorted by dst

// Order-preserving float<->uint encoding so unsigned atomicMax == float max.
__device__ __forceinline__ unsigned enc_f(float f) {
    unsigned u = __float_as_uint(f);
    return (u & 0x80000000u) ? ~u : (u | 0x80000000u);
}
__device__ __forceinline__ float dec_f(unsigned e) {
    unsigned u = (e & 0x80000000u) ? (e & 0x7FFFFFFFu) : ~e;
    return __uint_as_float(u);
}

__global__ void init_agg_kernel(long long tot, int n) {
    long long i = (long long)blockIdx.x * blockDim.x + threadIdx.x;
    long long stride = (long long)gridDim.x * blockDim.x;
    for (long long j = i; j < tot; j += stride)
        g_agg[j] = 0x007FFFFFu;   // enc(-inf)
    for (long long j = i; j < n; j += stride)
        g_cnt[j] = 0;
}

__global__ void hist_kernel(const int* __restrict__ ei, long long E, int N) {
    long long i = (long long)blockIdx.x * blockDim.x + threadIdx.x;
    long long stride = (long long)gridDim.x * blockDim.x;
    for (; i < E; i += stride) {
        int d = ei[E + i];
        d = min(max(d, 0), N - 1);
        atomicAdd(&g_cnt[d], 1);
    }
}

// single-block exclusive scan of g_cnt[0..n) -> g_cur (1024 threads)
__global__ void scan_kernel(int n) {
    __shared__ int part[1024];
    const int t = threadIdx.x;
    const int chunk = (n + 1023) >> 10;
    const int lo = min(t * chunk, n), hi = min(lo + chunk, n);
    int s = 0;
    for (int i = lo; i < hi; i++) s += g_cnt[i];
    part[t] = s;
    __syncthreads();
    for (int off = 1; off < 1024; off <<= 1) {
        int v = 0;
        if (t >= off) v = part[t - off];
        __syncthreads();
        if (t >= off) part[t] += v;
        __syncthreads();
    }
    int run = (t > 0) ? part[t - 1] : 0;
    for (int i = lo; i < hi; i++) { int c = g_cnt[i]; g_cur[i] = run; run += c; }
}

__global__ void scatter_kernel(const int* __restrict__ ei, long long E, int N) {
    long long i = (long long)blockIdx.x * blockDim.x + threadIdx.x;
    long long stride = (long long)gridDim.x * blockDim.x;
    for (; i < E; i += stride) {
        int d = ei[E + i];
        d = min(max(d, 0), N - 1);
        int pos = atomicAdd(&g_cur[d], 1);
        g_perm[pos] = (int)i;
    }
}

// Per-node precompute: Qd[n] = x[n]@(W1a - W1b) + b1 ; Qs[n] = x[n]@W1b
__global__ void __launch_bounds__(256)
precompute_kernel(const float* __restrict__ x, const float* __restrict__ W1,
                  const float* __restrict__ b1, int N)
{
    __shared__ float sWd[32 * 64];
    __shared__ float sWb[32 * 64];
    __shared__ float sX[4][32];

    const int tid = threadIdx.x;
    for (int i = tid; i < 32 * 64; i += 256) {
        float a = W1[i];
        float b = W1[i + 32 * 64];
        sWd[i] = a - b;
        sWb[i] = b;
    }
    __syncthreads();

    const int nodeBase = blockIdx.x * 64;
    const int nl  = tid >> 6;    // 0..3
    const int col = tid & 63;

    for (int it = 0; it < 16; it++) {
        if (tid < 128) {
            int rn = tid >> 5, k = tid & 31;
            int nn = nodeBase + it * 4 + rn;
            sX[rn][k] = (nn < N) ? x[(size_t)nn * INF_DIM + k] : 0.f;
        }
        __syncthreads();
        const int n = nodeBase + it * 4 + nl;
        float qd = b1[col], qs = 0.f;
        #pragma unroll
        for (int k = 0; k < 32; k++) {
            float xv = sX[nl][k];
            qd = fmaf(xv, sWd[k * 64 + col], qd);
            qs = fmaf(xv, sWb[k * 64 + col], qs);
        }
        if (n < N) {
            g_Qd[(size_t)n * HID + col] = qd;
            g_Qs[(size_t)n * HID + col] = qs;
        }
        __syncthreads();
    }
}

// Shared memory layout (float offsets):
//  sW2  [64*64]     @ 0      (scalar weights; dup2 in regs — R6-proven GEMM2)
//  sB2  [64]        @ 4096
//  sHT  [64][STR]   @ 4160   (relu(h) transposed: k-major, edges contiguous)
//  sDst [128] int   @ 12480
//  sSrc [128] int   @ 12608
//  sEa  [384]       @ 12736
//  sEid [128] int   @ 13120
#define SMEM_FLOATS 13248

__global__ void __launch_bounds__(THREADS, 2)
edge_mlp_kernel(const int* __restrict__ ei,    // harness canonicalizes int64 -> int32
                const float* __restrict__ ea,
                const float* __restrict__ W1,
                const float* __restrict__ W2, const float* __restrict__ b2,
                long long E, int N)
{
    extern __shared__ float sm[];
    float* sW2 = sm;
    float* sB2 = sm + 4096;
    float* sHT = sm + 4160;
    int*   sDst = (int*)(sm + 12480);
    int*   sSrc = (int*)(sm + 12608);
    float* sEa  = sm + 12736;
    int*   sEid = (int*)(sm + 13120);

    const int tid = threadIdx.x;

    // Load W2/b2 once per (persistent) block.
    for (int i = tid; i < HID * HID; i += THREADS) sW2[i] = W2[i];
    if (tid < HID) sB2[tid] = b2[tid];

    // Staging role: column group c8..c8+7 of one edge per iteration.
    const int c8 = (tid & 7) * 8;
    // W1c (ea rows 64..66) col-pairs for this thread's columns — registers.
    ull w1c[3][4];
    #pragma unroll
    for (int r = 0; r < 3; r++)
        #pragma unroll
        for (int j = 0; j < 4; j++)
            w1c[r][j] = *(const ull*)&W1[(64 + r) * HID + c8 + 2 * j];

    // GEMM2 role (R6-proven): 8 edges x 4 cols per thread.
    const int cg = tid & 15;
    const int eg = tid >> 4;
    const int c0 = cg * 4;
    const int e0 = eg * 8;

    const long long numTiles = (E + TILE_E - 1) / TILE_E;

    for (long long tile = blockIdx.x; tile < numTiles; tile += gridDim.x) {
        const long long base = tile * (long long)TILE_E;
        __syncthreads();   // previous tile fully consumed sHT/sDst

        // ---- indices (dst-sorted via perm) ----
        if (tid < TILE_E) {
            long long g = base + tid;
            int s = 0, d = 0, eid = 0;
            if (g < E) {
                eid = g_perm[g];
                s = ei[eid];
                d = ei[E + eid];
                s = min(max(s, 0), N - 1);   // safety clamp
                d = min(max(d, 0), N - 1);
            }
            sEid[tid] = eid; sSrc[tid] = s; sDst[tid] = d;
        }
        __syncthreads();
        // edge_attr gathered by sorted edge id (3 floats per edge)
        if (tid < TILE_E) {
            const int eid = sEid[tid];
            const bool ok = (base + tid < E);
            sEa[tid * 3 + 0] = ok ? ea[(size_t)eid * 3 + 0] : 0.f;
            sEa[tid * 3 + 1] = ok ? ea[(size_t)eid * 3 + 1] : 0.f;
            sEa[tid * 3 + 2] = ok ? ea[(size_t)eid * 3 + 2] : 0.f;
        }
        __syncthreads();

        // ---- stage h = relu(Qd[dst] + Qs[src] + ea@W1c), transposed k-major ----
        #pragma unroll
        for (int it = 0; it < 4; it++) {
            const int e = it * 32 + (tid >> 3);
            const float* qdp = g_Qd + (size_t)sDst[e] * HID + c8;
            const float* qsp = g_Qs + (size_t)sSrc[e] * HID + c8;
            ulonglong2 qdA = *(const ulonglong2*)qdp;
            ulonglong2 qdB = *(const ulonglong2*)(qdp + 4);
            ulonglong2 qsA = *(const ulonglong2*)qsp;
            ulonglong2 qsB = *(const ulonglong2*)(qsp + 4);
            ull h0 = add2(qdA.x, qsA.x);
            ull h1 = add2(qdA.y, qsA.y);
            ull h2 = add2(qdB.x, qsB.x);
            ull h3 = add2(qdB.y, qsB.y);
            ull ea0 = dup2(sEa[e * 3 + 0]);
            ull ea1 = dup2(sEa[e * 3 + 1]);
            ull ea2 = dup2(sEa[e * 3 + 2]);
            ffma2(h0, ea0, w1c[0][0]); ffma2(h0, ea1, w1c[1][0]); ffma2(h0, ea2, w1c[2][0]);
            ffma2(h1, ea0, w1c[0][1]); ffma2(h1, ea1, w1c[1][1]); ffma2(h1, ea2, w1c[2][1]);
            ffma2(h2, ea0, w1c[0][2]); ffma2(h2, ea1, w1c[1][2]); ffma2(h2, ea2, w1c[2][2]);
            ffma2(h3, ea0, w1c[0][3]); ffma2(h3, ea1, w1c[1][3]); ffma2(h3, ea2, w1c[2][3]);
            float2 v;
            v = unpk(h0);
            sHT[(c8 + 0) * STR + e] = fmaxf(v.x, 0.f);
            sHT[(c8 + 1) * STR + e] = fmaxf(v.y, 0.f);
            v = unpk(h1);
            sHT[(c8 + 2) * STR + e] = fmaxf(v.x, 0.f);
            sHT[(c8 + 3) * STR + e] = fmaxf(v.y, 0.f);
            v = unpk(h2);
            sHT[(c8 + 4) * STR + e] = fmaxf(v.x, 0.f);
            sHT[(c8 + 5) * STR + e] = fmaxf(v.y, 0.f);
            v = unpk(h3);
            sHT[(c8 + 6) * STR + e] = fmaxf(v.x, 0.f);
            sHT[(c8 + 7) * STR + e] = fmaxf(v.y, 0.f);
        }
        __syncthreads();

        // ---- GEMM2: msg = h @ W2 + b2  (R6-proven inner loop) ----
        ull acc[4][4];
        {
            ull bi0 = dup2(sB2[c0 + 0]), bi1 = dup2(sB2[c0 + 1]);
            ull bi2 = dup2(sB2[c0 + 2]), bi3 = dup2(sB2[c0 + 3]);
            #pragma unroll
            for (int p = 0; p < 4; p++) {
                acc[p][0] = bi0; acc[p][1] = bi1; acc[p][2] = bi2; acc[p][3] = bi3;
            }
        }
        #pragma unroll 4
        for (int k = 0; k < HID; k++) {
            const float* aT = &sHT[k * STR + e0];
            ull a0 = *(const ull*)(aT + 0);
            ull a1 = *(const ull*)(aT + 2);
            ull a2 = *(const ull*)(aT + 4);
            ull a3 = *(const ull*)(aT + 6);
            const float4 bv = *(const float4*)&sW2[k * HID + c0];
            ull b0 = dup2(bv.x), b1v = dup2(bv.y), b2v = dup2(bv.z), b3v = dup2(bv.w);
            ffma2(acc[0][0], a0, b0); ffma2(acc[0][1], a0, b1v); ffma2(acc[0][2], a0, b2v); ffma2(acc[0][3], a0, b3v);
            ffma2(acc[1][0], a1, b0); ffma2(acc[1][1], a1, b1v); ffma2(acc[1][2], a1, b2v); ffma2(acc[1][3], a1, b3v);
            ffma2(acc[2][0], a2, b0); ffma2(acc[2][1], a2, b1v); ffma2(acc[2][2], a2, b2v); ffma2(acc[2][3], a2, b3v);
            ffma2(acc[3][0], a3, b0); ffma2(acc[3][1], a3, b1v); ffma2(acc[3][2], a3, b2v); ffma2(acc[3][3], a3, b3v);
        }

        // ---- scatter with run folding: edges dst-sorted, fold equal-dst runs
        //      in registers, one atomicMax per (run, col) ----
        {
            int curd = -1;
            float m0 = 0.f, m1 = 0.f, m2 = 0.f, m3 = 0.f;
            #pragma unroll
            for (int p = 0; p < 4; p++) {
                float2 v0 = unpk(acc[p][0]), v1 = unpk(acc[p][1]);
                float2 v2 = unpk(acc[p][2]), v3 = unpk(acc[p][3]);
                #pragma unroll
                for (int sub = 0; sub < 2; sub++) {
                    const int e = e0 + 2 * p + sub;
                    if (base + e < E) {
                        const int d = sDst[e];
                        const float w0 = sub ? v0.y : v0.x;
                        const float w1 = sub ? v1.y : v1.x;
                        const float w2 = sub ? v2.y : v2.x;
                        const float w3 = sub ? v3.y : v3.x;
                        if (d == curd) {
                            m0 = fmaxf(m0, w0); m1 = fmaxf(m1, w1);
                            m2 = fmaxf(m2, w2); m3 = fmaxf(m3, w3);
                        } else {
                            if (curd >= 0) {
                                unsigned* dst = g_agg + (size_t)curd * HID + c0;
                                atomicMax(dst + 0, enc_f(m0));
                                atomicMax(dst + 1, enc_f(m1));
                                atomicMax(dst + 2, enc_f(m2));
                                atomicMax(dst + 3, enc_f(m3));
                            }
                            curd = d; m0 = w0; m1 = w1; m2 = w2; m3 = w3;
                        }
                    }
                }
            }
            if (curd >= 0) {
                unsigned* dst = g_agg + (size_t)curd * HID + c0;
                atomicMax(dst + 0, enc_f(m0));
                atomicMax(dst + 1, enc_f(m1));
                atomicMax(dst + 2, enc_f(m2));
                atomicMax(dst + 3, enc_f(m3));
            }
        }
    }
}

// Output stage: decode agg (empty -> 0), out = sigmoid(agg @ Wo + bo)
__global__ void out_kernel(const float* __restrict__ Wo,
                           const float* __restrict__ bo,
                           float* __restrict__ out, int N)
{
    __shared__ float sWo[64 * 16];
    __shared__ float sBo[16];
    __shared__ float sA[16 * 68];

    const int tid = threadIdx.x;
    for (int i = tid; i < 64 * 16; i += THREADS) sWo[i] = Wo[i];
    if (tid < 16) sBo[tid] = bo[tid];

    const int n0 = blockIdx.x * 16;
    for (int idx = tid; idx < 16 * 64; idx += THREADS) {
        int nl = idx >> 6, k = idx & 63;
        int n = n0 + nl;
        float f = 0.f;
        if (n < N) {
            float v = dec_f(g_agg[(size_t)n * HID + k]);
            f = isfinite(v) ? v : 0.f;   // empty segments -> 0 (PyG fill)
        }
        sA[nl * 68 + k] = f;
    }
    __syncthreads();

    const int nl = tid >> 4, o = tid & 15;
    const int n = n0 + nl;
    if (n < N) {
        float a = sBo[o];
        #pragma unroll
        for (int k = 0; k < 64; k++)
            a = fmaf(sA[nl * 68 + k], sWo[k * 16 + o], a);
        out[(size_t)n * 16 + o] = 1.f / (1.f + expf(-a));
    }
}

extern "C" void kernel_launch(void* const* d_in, const int* in_sizes, int n_in,
                              void* d_out, int out_size)
{
    const float* x  = (const float*)d_in[0];
    const int*   ei = (const int*)d_in[1];     // int64 in reference -> int32 here
    const float* ea = (const float*)d_in[2];
    const float* W1 = (const float*)d_in[3];
    const float* b1 = (const float*)d_in[4];
    const float* W2 = (const float*)d_in[5];
    const float* b2 = (const float*)d_in[6];
    const float* Wo = (const float*)d_in[7];
    const float* bo = (const float*)d_in[8];
    float* out = (float*)d_out;

    const int       N = in_sizes[0] / INF_DIM;
    const long long E = (long long)in_sizes[1] / 2;

    cudaFuncSetAttribute(edge_mlp_kernel,
                         cudaFuncAttributeMaxDynamicSharedMemorySize,
                         SMEM_FLOATS * (int)sizeof(float));

    const long long tot = (long long)N * HID;
    int initBlocks = (int)((tot + 256 * 8 - 1) / (256 * 8));
    if (initBlocks > 2048) initBlocks = 2048;
    int eBlocks = (int)((E + 256 * 4 - 1) / (256 * 4));
    if (eBlocks > 2048) eBlocks = 2048;

    init_agg_kernel<<<initBlocks, 256>>>(tot, N);
    hist_kernel<<<eBlocks, 256>>>(ei, E, N);
    scan_kernel<<<1, 1024>>>(N);
    scatter_kernel<<<eBlocks, 256>>>(ei, E, N);
    precompute_kernel<<<(N + 63) / 64, 256>>>(x, W1, b1, N);
    edge_mlp_kernel<<<296, THREADS, SMEM_FLOATS * sizeof(float)>>>(
        ei, ea, W1, W2, b2, E, N);
    out_kernel<<<(N + 15) / 16, THREADS>>>(Wo, bo, out, N);
}

// round 12
// speedup vs baseline: 1.0338x; 1.0338x over previous
#include <cuda_runtime.h>
#include <math.h>

#define TILE_E 128
#define HID 64
#define INF_DIM 32
#define THREADS 256
#define MAXN 51200
#define STR 130        // sHT row stride in floats (8B-aligned LDS.64, conflict-light)
#define HT_FLOATS (HID * STR)   // 8320

typedef unsigned long long ull;

// ---- packed f32x2 helpers (PTX-only; ptxas never auto-fuses) ----
__device__ __forceinline__ void ffma2(ull &acc, ull a, ull b) {
    asm("fma.rn.f32x2 %0, %1, %2, %0;" : "+l"(acc) : "l"(a), "l"(b));
}
__device__ __forceinline__ ull add2(ull a, ull b) {
    ull r; asm("add.rn.f32x2 %0, %1, %2;" : "=l"(r) : "l"(a), "l"(b)); return r;
}
__device__ __forceinline__ ull dup2(float v) {
    ull r; asm("mov.b64 %0, {%1, %1};" : "=l"(r) : "f"(v)); return r;
}
__device__ __forceinline__ float2 unpk(ull p) {
    float2 f; asm("mov.b64 {%0, %1}, %2;" : "=f"(f.x), "=f"(f.y) : "l"(p)); return f;
}

// Scratch (no cudaMalloc allowed)
__device__ unsigned int g_agg[(size_t)MAXN * HID];
__device__ float g_Qd[(size_t)MAXN * HID];   // x@(W1a-W1b) + b1
__device__ float g_Qs[(size_t)MAXN * HID];   // x@W1b

// Order-preserving float<->uint encoding so unsigned atomicMax == float max.
__device__ __forceinline__ unsigned enc_f(float f) {
    unsigned u = __float_as_uint(f);
    return (u & 0x80000000u) ? ~u : (u | 0x80000000u);
}
__device__ __forceinline__ float dec_f(unsigned e) {
    unsigned u = (e & 0x80000000u) ? (e & 0x7FFFFFFFu) : ~e;
    return __uint_as_float(u);
}

__global__ void init_agg_kernel(long long tot) {
    long long i = (long long)blockIdx.x * blockDim.x + threadIdx.x;
    long long stride = (long long)gridDim.x * blockDim.x;
    for (; i < tot; i += stride)
        g_agg[i] = 0x007FFFFFu;   // enc(-inf)
}

// profiler-alignment dummy (ncu captures the 4th launch; this makes edge_mlp 4th)
__global__ void dummy_kernel() {}

// Per-node precompute: Qd[n] = x[n]@(W1a - W1b) + b1 ; Qs[n] = x[n]@W1b
__global__ void __launch_bounds__(256)
precompute_kernel(const float* __restrict__ x, const float* __restrict__ W1,
                  const float* __restrict__ b1, int N)
{
    __shared__ float sWd[32 * 64];
    __shared__ float sWb[32 * 64];
    __shared__ float sX[4][32];

    const int tid = threadIdx.x;
    for (int i = tid; i < 32 * 64; i += 256) {
        float a = W1[i];
        float b = W1[i + 32 * 64];
        sWd[i] = a - b;
        sWb[i] = b;
    }
    __syncthreads();

    const int nodeBase = blockIdx.x * 64;
    const int nl  = tid >> 6;    // 0..3
    const int col = tid & 63;

    for (int it = 0; it < 16; it++) {
        if (tid < 128) {
            int rn = tid >> 5, k = tid & 31;
            int nn = nodeBase + it * 4 + rn;
            sX[rn][k] = (nn < N) ? x[(size_t)nn * INF_DIM + k] : 0.f;
        }
        __syncthreads();
        const int n = nodeBase + it * 4 + nl;
        float qd = b1[col], qs = 0.f;
        #pragma unroll
        for (int k = 0; k < 32; k++) {
            float xv = sX[nl][k];
            qd = fmaf(xv, sWd[k * 64 + col], qd);
            qs = fmaf(xv, sWb[k * 64 + col], qs);
        }
        if (n < N) {
            g_Qd[(size_t)n * HID + col] = qd;
            g_Qs[(size_t)n * HID + col] = qs;
        }
        __syncthreads();
    }
}

// Shared memory layout (float offsets):
//  sW2  [64*64]       @ 0
//  sB2  [64]          @ 4096
//  sHT  [2][64*STR]   @ 4160, 12480   (double-buffered h, k-major)
//  sDst [3][128] int  @ 20800
//  sSrc [3][128] int  @ 21184
//  sEa  [3][384]      @ 21568
#define SMEM_FLOATS 22720

__global__ void __launch_bounds__(THREADS, 2)
edge_mlp_kernel(const int* __restrict__ ei,    // harness canonicalizes int64 -> int32
                const float* __restrict__ ea,
                const float* __restrict__ W1,
                const float* __restrict__ W2, const float* __restrict__ b2,
                long long E, int N)
{
    extern __shared__ float sm[];
    float* sW2 = sm;
    float* sB2 = sm + 4096;
    float* sHT0 = sm + 4160;               // [2][HT_FLOATS]
    int*   sDst = (int*)(sm + 20800);      // [3][128]
    int*   sSrc = (int*)(sm + 21184);      // [3][128]
    float* sEa  = sm + 21568;              // [3][384]

    const int tid = threadIdx.x;

    // Load W2/b2 once per (persistent) block.
    for (int i = tid; i < HID * HID; i += THREADS) sW2[i] = W2[i];
    if (tid < HID) sB2[tid] = b2[tid];

    // Staging role: column group c8..c8+7 of one edge per iteration.
    const int c8 = (tid & 7) * 8;
    // W1c (ea rows 64..66) col-pairs for this thread's columns — registers.
    ull w1c[3][4];
    #pragma unroll
    for (int r = 0; r < 3; r++)
        #pragma unroll
        for (int j = 0; j < 4; j++)
            w1c[r][j] = *(const ull*)&W1[(64 + r) * HID + c8 + 2 * j];

    // GEMM2 role (R6-proven): 8 edges x 4 cols per thread.
    const int cg = tid & 15;
    const int eg = tid >> 4;
    const int c0 = cg * 4;
    const int e0 = eg * 8;

    const long long numTiles = (E + TILE_E - 1) / TILE_E;

    // ---- prologue: load idx/ea for this CTA's first tile into slot 0 ----
    {
        const long long t0 = blockIdx.x;
        if (t0 < numTiles) {
            const long long base = t0 * (long long)TILE_E;
            if (tid < TILE_E) {
                long long g = base + tid;
                int s = 0, d = 0;
                if (g < E) {
                    s = ei[g];
                    d = ei[E + g];
                    s = min(max(s, 0), N - 1);
                    d = min(max(d, 0), N - 1);
                }
                sSrc[tid] = s; sDst[tid] = d;
            } else if (tid < TILE_E + 96) {
                const int t = tid - TILE_E;
                const long long off = base * 3 + t * 4;
                if (off + 4 <= E * 3) {
                    *(float4*)&sEa[t * 4] = *(const float4*)&ea[off];
                } else {
                    #pragma unroll
                    for (int j = 0; j < 4; j++)
                        sEa[t * 4 + j] = (off + j < E * 3) ? ea[off + j] : 0.f;
                }
            }
        }
    }
    __syncthreads();

    int it8 = 0;  // iteration counter for buffer rotation
    for (long long tile = blockIdx.x; tile < numTiles; tile += gridDim.x, it8++) {
        const long long base = tile * (long long)TILE_E;
        const int slot = it8 % 3;
        const int nslot = (it8 + 1) % 3;
        float* sHT = sHT0 + (it8 & 1) * HT_FLOATS;
        const int* dstS = sDst + slot * TILE_E;
        const int* srcS = sSrc + slot * TILE_E;
        const float* eaS = sEa + slot * 384;

        // ---- stage h = relu(Qd[dst] + Qs[src] + ea@W1c) into sHT (k-major) ----
        #pragma unroll
        for (int it = 0; it < 4; it++) {
            const int e = it * 32 + (tid >> 3);
            const float* qdp = g_Qd + (size_t)dstS[e] * HID + c8;
            const float* qsp = g_Qs + (size_t)srcS[e] * HID + c8;
            ulonglong2 qdA = *(const ulonglong2*)qdp;
            ulonglong2 qdB = *(const ulonglong2*)(qdp + 4);
            ulonglong2 qsA = *(const ulonglong2*)qsp;
            ulonglong2 qsB = *(const ulonglong2*)(qsp + 4);
            ull h0 = add2(qdA.x, qsA.x);
            ull h1 = add2(qdA.y, qsA.y);
            ull h2 = add2(qdB.x, qsB.x);
            ull h3 = add2(qdB.y, qsB.y);
            ull ea0 = dup2(eaS[e * 3 + 0]);
            ull ea1 = dup2(eaS[e * 3 + 1]);
            ull ea2 = dup2(eaS[e * 3 + 2]);
            ffma2(h0, ea0, w1c[0][0]); ffma2(h0, ea1, w1c[1][0]); ffma2(h0, ea2, w1c[2][0]);
            ffma2(h1, ea0, w1c[0][1]); ffma2(h1, ea1, w1c[1][1]); ffma2(h1, ea2, w1c[2][1]);
            ffma2(h2, ea0, w1c[0][2]); ffma2(h2, ea1, w1c[1][2]); ffma2(h2, ea2, w1c[2][2]);
            ffma2(h3, ea0, w1c[0][3]); ffma2(h3, ea1, w1c[1][3]); ffma2(h3, ea2, w1c[2][3]);
            float2 v;
            v = unpk(h0);
            sHT[(c8 + 0) * STR + e] = fmaxf(v.x, 0.f);
            sHT[(c8 + 1) * STR + e] = fmaxf(v.y, 0.f);
            v = unpk(h1);
            sHT[(c8 + 2) * STR + e] = fmaxf(v.x, 0.f);
            sHT[(c8 + 3) * STR + e] = fmaxf(v.y, 0.f);
            v = unpk(h2);
            sHT[(c8 + 4) * STR + e] = fmaxf(v.x, 0.f);
            sHT[(c8 + 5) * STR + e] = fmaxf(v.y, 0.f);
            v = unpk(h3);
            sHT[(c8 + 6) * STR + e] = fmaxf(v.x, 0.f);
            sHT[(c8 + 7) * STR + e] = fmaxf(v.y, 0.f);
        }

        // ---- prefetch idx/ea for next tile into the next slot (no sync yet) ----
        {
            const long long nt = tile + gridDim.x;
            if (nt < numTiles) {
                const long long nbase = nt * (long long)TILE_E;
                if (tid < TILE_E) {
                    long long g = nbase + tid;
                    int s = 0, d = 0;
                    if (g < E) {
                        s = ei[g];
                        d = ei[E + g];
                        s = min(max(s, 0), N - 1);
                        d = min(max(d, 0), N - 1);
                    }
                    sSrc[nslot * TILE_E + tid] = s;
                    sDst[nslot * TILE_E + tid] = d;
                } else if (tid < TILE_E + 96) {
                    const int t = tid - TILE_E;
                    const long long off = nbase * 3 + t * 4;
                    if (off + 4 <= E * 3) {
                        *(float4*)&sEa[nslot * 384 + t * 4] = *(const float4*)&ea[off];
                    } else {
                        #pragma unroll
                        for (int j = 0; j < 4; j++)
                            sEa[nslot * 384 + t * 4 + j] = (off + j < E * 3) ? ea[off + j] : 0.f;
                    }
                }
            }
        }

        __syncthreads();   // sHT(t) + idx(t+1) ready; buffers from t-1 reusable

        // ---- GEMM2: msg = h @ W2 + b2  (R6-proven inner loop) ----
        ull acc[4][4];
        {
            ull bi0 = dup2(sB2[c0 + 0]), bi1 = dup2(sB2[c0 + 1]);
            ull bi2 = dup2(sB2[c0 + 2]), bi3 = dup2(sB2[c0 + 3]);
            #pragma unroll
            for (int p = 0; p < 4; p++) {
                acc[p][0] = bi0; acc[p][1] = bi1; acc[p][2] = bi2; acc[p][3] = bi3;
            }
        }
        #pragma unroll 4
        for (int k = 0; k < HID; k++) {
            const float* aT = &sHT[k * STR + e0];
            ull a0 = *(const ull*)(aT + 0);
            ull a1 = *(const ull*)(aT + 2);
            ull a2 = *(const ull*)(aT + 4);
            ull a3 = *(const ull*)(aT + 6);
            const float4 bv = *(const float4*)&sW2[k * HID + c0];
            ull b0 = dup2(bv.x), b1v = dup2(bv.y), b2v = dup2(bv.z), b3v = dup2(bv.w);
            ffma2(acc[0][0], a0, b0); ffma2(acc[0][1], a0, b1v); ffma2(acc[0][2], a0, b2v); ffma2(acc[0][3], a0, b3v);
            ffma2(acc[1][0], a1, b0); ffma2(acc[1][1], a1, b1v); ffma2(acc[1][2], a1, b2v); ffma2(acc[1][3], a1, b3v);
            ffma2(acc[2][0], a2, b0); ffma2(acc[2][1], a2, b1v); ffma2(acc[2][2], a2, b2v); ffma2(acc[2][3], a2, b3v);
            ffma2(acc[3][0], a3, b0); ffma2(acc[3][1], a3, b1v); ffma2(acc[3][2], a3, b2v); ffma2(acc[3][3], a3, b3v);
        }

        // ---- scatter: atomic float-max via uint encoding (RED.MAX.U32) ----
        #pragma unroll
        for (int p = 0; p < 4; p++) {
            const int eA = e0 + 2 * p;
            float2 v0 = unpk(acc[p][0]), v1 = unpk(acc[p][1]);
            float2 v2 = unpk(acc[p][2]), v3 = unpk(acc[p][3]);
            if (base + eA < E) {
                unsigned* d = g_agg + (size_t)dstS[eA] * HID + c0;
                atomicMax(d + 0, enc_f(v0.x));
                atomicMax(d + 1, enc_f(v1.x));
                atomicMax(d + 2, enc_f(v2.x));
                atomicMax(d + 3, enc_f(v3.x));
            }
            if (base + eA + 1 < E) {
                unsigned* d = g_agg + (size_t)dstS[eA + 1] * HID + c0;
                atomicMax(d + 0, enc_f(v0.y));
                atomicMax(d + 1, enc_f(v1.y));
                atomicMax(d + 2, enc_f(v2.y));
                atomicMax(d + 3, enc_f(v3.y));
            }
        }
    }
}

// Output stage: decode agg (empty -> 0), out = sigmoid(agg @ Wo + bo)
__global__ void out_kernel(const float* __restrict__ Wo,
                           const float* __restrict__ bo,
                           float* __restrict__ out, int N)
{
    __shared__ float sWo[64 * 16];
    __shared__ float sBo[16];
    __shared__ float sA[16 * 68];

    const int tid = threadIdx.x;
    for (int i = tid; i < 64 * 16; i += THREADS) sWo[i] = Wo[i];
    if (tid < 16) sBo[tid] = bo[tid];

    const int n0 = blockIdx.x * 16;
    for (int idx = tid; idx < 16 * 64; idx += THREADS) {
        int nl = idx >> 6, k = idx & 63;
        int n = n0 + nl;
        float f = 0.f;
        if (n < N) {
            float v = dec_f(g_agg[(size_t)n * HID + k]);
            f = isfinite(v) ? v : 0.f;   // empty segments -> 0 (PyG fill)
        }
        sA[nl * 68 + k] = f;
    }
    __syncthreads();

    const int nl = tid >> 4, o = tid & 15;
    const int n = n0 + nl;
    if (n < N) {
        float a = sBo[o];
        #pragma unroll
        for (int k = 0; k < 64; k++)
            a = fmaf(sA[nl * 68 + k], sWo[k * 16 + o], a);
        out[(size_t)n * 16 + o] = 1.f / (1.f + expf(-a));
    }
}

extern "C" void kernel_launch(void* const* d_in, const int* in_sizes, int n_in,
                              void* d_out, int out_size)
{
    const float* x  = (const float*)d_in[0];
    const int*   ei = (const int*)d_in[1];     // int64 in reference -> int32 here
    const float* ea = (const float*)d_in[2];
    const float* W1 = (const float*)d_in[3];
    const float* b1 = (const float*)d_in[4];
    const float* W2 = (const float*)d_in[5];
    const float* b2 = (const float*)d_in[6];
    const float* Wo = (const float*)d_in[7];
    const float* bo = (const float*)d_in[8];
    float* out = (float*)d_out;

    const int       N = in_sizes[0] / INF_DIM;
    const long long E = (long long)in_sizes[1] / 2;

    cudaFuncSetAttribute(edge_mlp_kernel,
                         cudaFuncAttributeMaxDynamicSharedMemorySize,
                         SMEM_FLOATS * (int)sizeof(float));

    const long long tot = (long long)N * HID;
    int initBlocks = (int)((tot + 256 * 8 - 1) / (256 * 8));
    if (initBlocks > 2048) initBlocks = 2048;

    init_agg_kernel<<<initBlocks, 256>>>(tot);                       // launch 1
    precompute_kernel<<<(N + 63) / 64, 256>>>(x, W1, b1, N);         // launch 2
    dummy_kernel<<<1, 32>>>();                                       // launch 3
    edge_mlp_kernel<<<296, THREADS, SMEM_FLOATS * sizeof(float)>>>(  // launch 4 (profiled)
        ei, ea, W1, W2, b2, E, N);
    out_kernel<<<(N + 15) / 16, THREADS>>>(Wo, bo, out, N);          // launch 5
}